// round 15
// baseline (speedup 1.0000x reference)
#include <cuda_runtime.h>
#include <cuda_fp16.h>
#include <cstdint>

#define Nn 100000
#define Ee 3200000
#define CLIND 64
#define MELD 1280
#define Hd 128
#define Cd 4
#define XCATD 192

// ---------------- scratch (device globals; no allocation) ----------------
__device__ __half g_melh[(size_t)Nn * Hd];
__device__ __half g_x1[(size_t)Nn * Hd];
__device__ __half g_x2[(size_t)Nn * Hd];
__device__ __half g_aggh[(size_t)Nn * Hd];    // layer-1 aggregate (fp16)
__device__ __half g_wm[(size_t)Hd * MELD];    // fp16 weights
__device__ __half g_wc[(size_t)Hd * XCATD];
__device__ __half g_wl1[(size_t)Hd * Hd];
__device__ __half g_wr1[(size_t)Hd * Hd];
__device__ int   g_deg[Nn];
__device__ int   g_rowstart[Nn + 1];
__device__ int   g_cursor[Nn];
__device__ int   g_csr[Ee];
__device__ float g_invdeg[Nn];
__device__ int   g_part[128];
__device__ int   g_edge_first;

// ---------------- sniff which 6.4M input is edge_index ----------------
__global__ void k_sniff(const int* __restrict__ c0) {
    __shared__ int ok;
    if (threadIdx.x == 0) ok = 1;
    __syncthreads();
    for (int i = threadIdx.x; i < 4096; i += blockDim.x) {
        unsigned v = (unsigned)c0[i];
        if (v >= (unsigned)Nn) ok = 0;
    }
    __syncthreads();
    if (threadIdx.x == 0) g_edge_first = ok;
}

// ---------------- weight fp32 -> fp16 ----------------
__global__ void k_cvtw(const float* __restrict__ src, __half* __restrict__ dst, int n) {
    int i = blockIdx.x * blockDim.x + threadIdx.x;
    if (i * 4 < n) {
        float4 v = *(const float4*)&src[i * 4];
        __half2 h0 = __floats2half2_rn(v.x, v.y);
        __half2 h1 = __floats2half2_rn(v.z, v.w);
        *(uint2*)&dst[i * 4] = make_uint2(*(uint32_t*)&h0, *(uint32_t*)&h1);
    }
}

// ---------------- graph preprocessing ----------------
__global__ void k_zerodeg() {
    int i = blockIdx.x * blockDim.x + threadIdx.x;
    if (i < Nn) g_deg[i] = 0;
}
__global__ void k_degree(const int* __restrict__ c0, const int* __restrict__ c1) {
    const int* ei = g_edge_first ? c0 : c1;
    int e = blockIdx.x * blockDim.x + threadIdx.x;
    if (e < Ee) {
        unsigned dst = (unsigned)ei[Ee + e];
        if (dst < (unsigned)Nn) atomicAdd(&g_deg[dst], 1);
    }
}
__global__ void k_scan1() {
    __shared__ int s[1024];
    int i = blockIdx.x * 1024 + threadIdx.x;
    int v = (i < Nn) ? g_deg[i] : 0;
    s[threadIdx.x] = v;
    __syncthreads();
    #pragma unroll
    for (int off = 1; off < 1024; off <<= 1) {
        int t = (threadIdx.x >= off) ? s[threadIdx.x - off] : 0;
        __syncthreads();
        s[threadIdx.x] += t;
        __syncthreads();
    }
    if (i < Nn) g_rowstart[i] = s[threadIdx.x] - v;
    if (threadIdx.x == 1023) g_part[blockIdx.x] = s[1023];
}
__global__ void k_scan2(int nb) {
    if (blockIdx.x == 0 && threadIdx.x == 0) {
        int acc = 0;
        for (int b = 0; b < nb; b++) { int t = g_part[b]; g_part[b] = acc; acc += t; }
        g_rowstart[Nn] = acc;
    }
}
__global__ void k_scan3() {
    int i = blockIdx.x * 1024 + threadIdx.x;
    if (i < Nn) {
        g_rowstart[i] += g_part[blockIdx.x];
        g_cursor[i] = 0;
        int d = g_deg[i];
        g_invdeg[i] = 1.0f / (float)(d > 1 ? d : 1);
    }
}
__global__ void k_fill(const int* __restrict__ c0, const int* __restrict__ c1) {
    const int* ei = g_edge_first ? c0 : c1;
    int e = blockIdx.x * blockDim.x + threadIdx.x;
    if (e < Ee) {
        unsigned dst = (unsigned)ei[Ee + e];
        unsigned src = (unsigned)ei[e];
        if (dst < (unsigned)Nn) {
            int pos = atomicAdd(&g_cursor[dst], 1);
            int idx = g_rowstart[dst] + pos;
            if (idx >= 0 && idx < Ee)
                g_csr[idx] = (src < (unsigned)Nn) ? (int)src : 0;
        }
    }
}

// ---------------- HMMA fp16 dual-segment GEMM ----------------
__device__ __forceinline__ uint32_t smem_u32(const void* p) {
    uint32_t a;
    asm("{ .reg .u64 t; cvta.to.shared.u64 t, %1; cvt.u32.u64 %0, t; }" : "=r"(a) : "l"(p));
    return a;
}
__device__ __forceinline__ void ldsm4(uint32_t* r, uint32_t addr) {
    asm volatile("ldmatrix.sync.aligned.m8n8.x4.shared.b16 {%0,%1,%2,%3}, [%4];"
                 : "=r"(r[0]), "=r"(r[1]), "=r"(r[2]), "=r"(r[3]) : "r"(addr));
}
__device__ __forceinline__ void mma16816(float* c, const uint32_t* a, uint32_t b0, uint32_t b1) {
    asm volatile(
        "mma.sync.aligned.m16n8k16.row.col.f32.f16.f16.f32 "
        "{%0,%1,%2,%3}, {%4,%5,%6,%7}, {%8,%9}, {%0,%1,%2,%3};"
        : "+f"(c[0]), "+f"(c[1]), "+f"(c[2]), "+f"(c[3])
        : "r"(a[0]), "r"(a[1]), "r"(a[2]), "r"(a[3]), "r"(b0), "r"(b1));
}
__device__ __forceinline__ uint4 cvt8h(const float* f) {
    uint32_t u[4];
    #pragma unroll
    for (int i = 0; i < 4; i++) {
        __half2 h = __floats2half2_rn(f[2 * i], f[2 * i + 1]);
        u[i] = *(uint32_t*)&h;
    }
    return make_uint4(u[0], u[1], u[2], u[3]);
}

template <bool A0H, bool A1H>
__global__ void __launch_bounds__(256, 2) k_mm(
    const void* __restrict__ A0a, const void* __restrict__ A0b, int lda0,
    const __half* __restrict__ W0, int ldw0, int kc0,
    const void* __restrict__ A1, int lda1,
    const __half* __restrict__ W1, int ldw1, int kc1,
    const float* __restrict__ bias, __half* __restrict__ C,
    int doRelu, int M)
{
    __shared__ __align__(16) char sA[16384];   // 128 rows x 64 halves, SW128
    __shared__ __align__(16) char sB[16384];
    const uint32_t sAu = smem_u32(sA);
    const uint32_t sBu = smem_u32(sB);
    int tid = threadIdx.x;
    int lane = tid & 31, wid = tid >> 5;
    int warpM = wid & 3, warpN = wid >> 2;
    int rowBase = blockIdx.x * 128;
    const void* A0 = g_edge_first ? A0b : A0a;

    float acc[2][8][4];
    #pragma unroll
    for (int mt = 0; mt < 2; mt++)
        #pragma unroll
        for (int nt = 0; nt < 8; nt++)
            #pragma unroll
            for (int j = 0; j < 4; j++) acc[mt][nt][j] = 0.f;

    const int aRow[2] = { warpM * 32 + (lane & 15), warpM * 32 + 16 + (lane & 15) };
    const int aColb = ((lane >> 4) & 1) * 16;
    const int bNbase = warpN * 64 + ((lane >> 4) << 3) + (lane & 7);
    const int bColb = ((lane >> 3) & 1) * 16;

    for (int seg = 0; seg < 2; seg++) {
        const void* A = seg ? A1 : A0;
        const __half* W = seg ? W1 : W0;
        const int lda = seg ? lda1 : lda0;
        const int ldw = seg ? ldw1 : ldw0;
        const int kc  = seg ? kc1 : kc0;
        const bool ah = seg ? A1H : A0H;
        for (int c = 0; c < kc; c++) {
            const int k0 = c * 64;
            #pragma unroll
            for (int it = 0; it < 4; it++) {
                int g = tid + it * 256;
                int r = g >> 3, cq = (g & 7) * 8;
                int rg = rowBase + r; if (rg > M - 1) rg = M - 1;
                uint32_t off = r * 128 + cq * 2;
                uint32_t sw = off ^ ((off >> 3) & 0x70);
                if (ah) {
                    const __half* ap = (const __half*)A + (size_t)rg * lda + k0 + cq;
                    *(uint4*)(sA + sw) = *(const uint4*)ap;
                } else {
                    const float* ap = (const float*)A + (size_t)rg * lda + k0 + cq;
                    float4 v0 = *(const float4*)ap;
                    float4 v1 = *(const float4*)(ap + 4);
                    float fa[8] = {v0.x, v0.y, v0.z, v0.w, v1.x, v1.y, v1.z, v1.w};
                    *(uint4*)(sA + sw) = cvt8h(fa);
                }
                const __half* wp = W + (size_t)r * ldw + k0 + cq;
                *(uint4*)(sB + sw) = *(const uint4*)wp;
            }
            __syncthreads();
            #pragma unroll
            for (int kb = 0; kb < 4; kb++) {
                uint32_t a[2][4];
                #pragma unroll
                for (int mt = 0; mt < 2; mt++) {
                    uint32_t off = aRow[mt] * 128 + kb * 32 + aColb;
                    off ^= (off >> 3) & 0x70;
                    ldsm4(a[mt], sAu + off);
                }
                uint32_t b[4][4];
                #pragma unroll
                for (int ng = 0; ng < 4; ng++) {
                    uint32_t off = (bNbase + ng * 16) * 128 + kb * 32 + bColb;
                    off ^= (off >> 3) & 0x70;
                    ldsm4(b[ng], sBu + off);
                }
                #pragma unroll
                for (int mt = 0; mt < 2; mt++)
                    #pragma unroll
                    for (int nt = 0; nt < 8; nt++)
                        mma16816(acc[mt][nt], a[mt], b[nt >> 1][(nt & 1) * 2], b[nt >> 1][(nt & 1) * 2 + 1]);
            }
            __syncthreads();
        }
    }

    #pragma unroll
    for (int mt = 0; mt < 2; mt++) {
        int r0 = rowBase + warpM * 32 + mt * 16 + (lane >> 2);
        int r1 = r0 + 8;
        #pragma unroll
        for (int nt = 0; nt < 8; nt++) {
            int col = warpN * 64 + nt * 8 + (lane & 3) * 2;
            float b0 = bias[col], b1 = bias[col + 1];
            float v0 = acc[mt][nt][0] + b0, v1 = acc[mt][nt][1] + b1;
            float v2 = acc[mt][nt][2] + b0, v3 = acc[mt][nt][3] + b1;
            if (doRelu) {
                v0 = fmaxf(v0, 0.f); v1 = fmaxf(v1, 0.f);
                v2 = fmaxf(v2, 0.f); v3 = fmaxf(v3, 0.f);
            }
            __half2 h0 = __floats2half2_rn(v0, v1);
            __half2 h1 = __floats2half2_rn(v2, v3);
            if (r0 < M) *(__half2*)&C[(size_t)r0 * Hd + col] = h0;
            if (r1 < M) *(__half2*)&C[(size_t)r1 * Hd + col] = h1;
        }
    }
}

// ---------------- mean aggregation: warp/node, half-warp per edge, uint4 loads ----
__global__ void k_agg(const __half* __restrict__ X, __half* __restrict__ OUT) {
    int w = (blockIdx.x * blockDim.x + threadIdx.x) >> 5;
    int lane = threadIdx.x & 31;
    if (w >= Nn) return;
    int s = g_rowstart[w], e = g_rowstart[w + 1];
    int half = lane >> 4;            // 0: even edges, 1: odd edges
    int c8 = (lane & 15) * 8;        // 8 halves per lane
    float a[8] = {0.f, 0.f, 0.f, 0.f, 0.f, 0.f, 0.f, 0.f};
    for (int i = s + half; i < e; i += 2) {
        int src = g_csr[i];
        uint4 u = *(const uint4*)&X[(size_t)src * Hd + c8];
        const __half2* h = (const __half2*)&u;
        #pragma unroll
        for (int j = 0; j < 4; j++) {
            float2 f = __half22float2(h[j]);
            a[2 * j] += f.x; a[2 * j + 1] += f.y;
        }
    }
    #pragma unroll
    for (int j = 0; j < 8; j++)
        a[j] += __shfl_xor_sync(0xFFFFFFFFu, a[j], 16);
    float inv = g_invdeg[w];
    if (half == 0) {
        __half2 h0 = __floats2half2_rn(a[0] * inv, a[1] * inv);
        __half2 h1 = __floats2half2_rn(a[2] * inv, a[3] * inv);
        __half2 h2 = __floats2half2_rn(a[4] * inv, a[5] * inv);
        __half2 h3 = __floats2half2_rn(a[6] * inv, a[7] * inv);
        *(uint4*)&OUT[(size_t)w * Hd + c8] =
            make_uint4(*(uint32_t*)&h0, *(uint32_t*)&h1, *(uint32_t*)&h2, *(uint32_t*)&h3);
    }
}

// ---------------- fused layer-2: gather x2 neighbors + sage2 projection ----------
__global__ void k_final(const __half* __restrict__ x2p,
                        const float* __restrict__ Wl2, const float* __restrict__ bl2,
                        const float* __restrict__ Wr2, float* __restrict__ out) {
    __shared__ float sWl[4 * Hd], sWr[4 * Hd];
    int tid = threadIdx.x;
    for (int i = tid; i < 4 * Hd; i += blockDim.x) {
        sWl[i] = Wl2[i];
        sWr[i] = Wr2[i];
    }
    __syncthreads();
    int w = (blockIdx.x * blockDim.x + tid) >> 5;
    int lane = tid & 31;
    if (w >= Nn) return;
    int s = g_rowstart[w], e = g_rowstart[w + 1];
    int half = lane >> 4;
    int c8 = (lane & 15) * 8;
    float a[8] = {0.f, 0.f, 0.f, 0.f, 0.f, 0.f, 0.f, 0.f};
    for (int i = s + half; i < e; i += 2) {
        int src = g_csr[i];
        uint4 u = *(const uint4*)&x2p[(size_t)src * Hd + c8];
        const __half2* h = (const __half2*)&u;
        #pragma unroll
        for (int j = 0; j < 4; j++) {
            float2 f = __half22float2(h[j]);
            a[2 * j] += f.x; a[2 * j + 1] += f.y;
        }
    }
    #pragma unroll
    for (int j = 0; j < 8; j++)
        a[j] += __shfl_xor_sync(0xFFFFFFFFu, a[j], 16);
    float inv = g_invdeg[w];
    #pragma unroll
    for (int j = 0; j < 8; j++) a[j] *= inv;
    // own row (both halves read same cols -> broadcast)
    float x[8];
    {
        uint4 u = *(const uint4*)&x2p[(size_t)w * Hd + c8];
        const __half2* h = (const __half2*)&u;
        #pragma unroll
        for (int j = 0; j < 4; j++) {
            float2 f = __half22float2(h[j]);
            x[2 * j] = f.x; x[2 * j + 1] = f.y;
        }
    }
    float res[4];
    #pragma unroll
    for (int c = 0; c < 4; c++) {
        const float* wl = &sWl[c * Hd + c8];
        const float* wr = &sWr[c * Hd + c8];
        float p = 0.f;
        #pragma unroll
        for (int j = 0; j < 8; j++)
            p += a[j] * wl[j] + x[j] * wr[j];
        // reduce within each 16-lane group (both halves identical afterwards)
        #pragma unroll
        for (int off = 8; off >= 1; off >>= 1)
            p += __shfl_xor_sync(0xFFFFFFFFu, p, off);
        res[c] = p;
    }
    if (lane < 4) out[(size_t)w * 4 + lane] = res[lane] + bl2[lane];
}

// ---------------- launch ----------------
extern "C" void kernel_launch(void* const* d_in, const int* in_sizes, int n_in,
                              void* d_out, int out_size)
{
    void* p;
    __half *melh, *x1, *x2, *aggh, *wm, *wc, *wl1, *wr1;
    cudaGetSymbolAddress(&p, g_melh); melh = (__half*)p;
    cudaGetSymbolAddress(&p, g_x1);   x1 = (__half*)p;
    cudaGetSymbolAddress(&p, g_x2);   x2 = (__half*)p;
    cudaGetSymbolAddress(&p, g_aggh); aggh = (__half*)p;
    cudaGetSymbolAddress(&p, g_wm);   wm = (__half*)p;
    cudaGetSymbolAddress(&p, g_wc);   wc = (__half*)p;
    cudaGetSymbolAddress(&p, g_wl1);  wl1 = (__half*)p;
    cudaGetSymbolAddress(&p, g_wr1);  wr1 = (__half*)p;

    const float *cand0 = nullptr, *cand1 = nullptr;
    const float *mel = nullptr;
    const float *Wm = nullptr, *bm = nullptr, *Wc = nullptr, *bc = nullptr;
    const float *Wl1 = nullptr, *bl1 = nullptr, *Wr1 = nullptr;
    const float *Wl2 = nullptr, *bl2 = nullptr, *Wr2 = nullptr;

    bool have128M = false, have512M = false;
    for (int i = 0; i < n_in; i++) {
        long long s = in_sizes[i];
        if (s == 128000000LL) have128M = true;
        if (s == 512000000LL) have512M = true;
    }
    long long div = have128M ? 1 : (have512M ? 4 : 0);
    if (div) {
        for (int i = 0; i < n_in; i++) {
            long long s = in_sizes[i] / div;
            const void* q = d_in[i];
            if (s == 128000000LL)    { mel = (const float*)q; }
            else if (s == 6400000LL) { if (!cand0) cand0 = (const float*)q; else cand1 = (const float*)q; }
            else if (s == 163840LL)  { Wm = (const float*)q; }
            else if (s == 24576LL)   { Wc = (const float*)q; }
            else if (s == 16384LL)   { if (!Wl1) Wl1 = (const float*)q; else Wr1 = (const float*)q; }
            else if (s == 512LL)     { if (!Wl2) Wl2 = (const float*)q; else Wr2 = (const float*)q; }
            else if (s == 128LL)     { if (!bm) bm = (const float*)q; else if (!bc) bc = (const float*)q; else bl1 = (const float*)q; }
            else if (s == 4LL)       { bl2 = (const float*)q; }
        }
    }
    if (!mel || !Wm || !Wc || !Wl1 || !Wr1 || !Wl2 || !Wr2 ||
        !bm || !bc || !bl1 || !bl2 || !cand0 || !cand1) {
        cand0 = (const float*)d_in[0];
        mel   = (const float*)d_in[1];
        cand1 = (const float*)d_in[2];
        Wm  = (const float*)d_in[3];  bm  = (const float*)d_in[4];
        Wc  = (const float*)d_in[5];  bc  = (const float*)d_in[6];
        Wl1 = (const float*)d_in[7];  bl1 = (const float*)d_in[8];
        Wr1 = (const float*)d_in[9];
        Wl2 = (const float*)d_in[10]; bl2 = (const float*)d_in[11];
        Wr2 = (const float*)d_in[12];
    }
    float* out = (float*)d_out;

    const int NB = (Nn + 1023) / 1024;
    const int EB = (Ee + 255) / 256;
    const int MM_BLKS = (Nn + 127) / 128;
    const int WARP_BLKS = (Nn + 7) / 8;

    k_sniff<<<1, 256>>>((const int*)cand0);

    // weights -> fp16 (tiny)
    k_cvtw<<<(163840 / 4 + 255) / 256, 256>>>(Wm, wm, 163840);
    k_cvtw<<<(24576 / 4 + 255) / 256, 256>>>(Wc, wc, 24576);
    k_cvtw<<<(16384 / 4 + 255) / 256, 256>>>(Wl1, wl1, 16384);
    k_cvtw<<<(16384 / 4 + 255) / 256, 256>>>(Wr1, wr1, 16384);

    // graph preprocessing
    k_zerodeg<<<NB, 1024>>>();
    k_degree<<<EB, 256>>>((const int*)cand0, (const int*)cand1);
    k_scan1<<<NB, 1024>>>();
    k_scan2<<<1, 32>>>(NB);
    k_scan3<<<NB, 1024>>>();
    k_fill<<<EB, 256>>>((const int*)cand0, (const int*)cand1);

    // mel_h = relu(mel @ Wm^T + bm)
    k_mm<false, false><<<MM_BLKS, 256>>>(mel, mel, MELD, wm, MELD, MELD / 64,
                                         nullptr, 0, nullptr, 0, 0,
                                         bm, melh, 1, Nn);
    // x1 = relu(clinical @ Wc[:,:64]^T + mel_h @ Wc[:,64:]^T + bc)
    k_mm<false, true><<<MM_BLKS, 256>>>(cand0, cand1, CLIND, wc, XCATD, 1,
                                        melh, Hd, wc + CLIND, XCATD, 2,
                                        bc, x1, 1, Nn);
    // sage1: x2 = relu(agg @ Wl1^T + x1 @ Wr1^T + bl1)
    k_agg<<<WARP_BLKS, 256>>>(x1, aggh);
    k_mm<true, true><<<MM_BLKS, 256>>>(aggh, aggh, Hd, wl1, Hd, 2,
                                       x1, Hd, wr1, Hd, 2,
                                       bl1, x2, 1, Nn);
    // sage2: fused gather + projection
    k_final<<<WARP_BLKS, 256>>>(x2, Wl2, bl2, Wr2, out);
}